// round 16
// baseline (speedup 1.0000x reference)
#include <cuda_runtime.h>
#include <math.h>

#define TOKENS   16384
#define HIDDEN   4096
#define NEXPERTS 64
#define MT       128                 // tokens per CTA
#define KB       16                  // k-chunk
#define NCH      (HIDDEN / KB)       // 256 chunks
#define NTHREADS 256
#define LROW     65                  // logits smem row stride (conflict-free scan)
#define BUFSZ    (KB * 128)          // floats per buffer (x: 16k x 128 tok; w: 16k x 128 dup)

#define FMA2(d, a, b, c) \
    asm("fma.rn.f32x2 %0, %1, %2, %3;" : "=l"(d) : "l"(a), "l"(b), "l"(c))

__global__ __launch_bounds__(NTHREADS, 1)
void Router_4964982194280_kernel(const float* __restrict__ x,
                                 const float* __restrict__ w,
                                 float* __restrict__ out, int out_size)
{
    // smem: two double-buffered tiles (x: 2*BUFSZ, w-dup: 2*BUFSZ) = 8192 floats,
    // later overlaid by logits tile 128 x 65 = 8320 floats. 33.3 KB static.
    __shared__ __align__(16) float smem[MT * LROW];
    float* xs = smem;                 // [2][KB][128]  x transposed, swizzled
    float* ws = smem + 2 * BUFSZ;     // [2][KB][128]  w duplicated pairs, swizzled

    const int tid = threadIdx.x;
    const int tx  = tid & 15;         // expert group: experts 4*tx .. 4*tx+3
    const int ty  = tid >> 4;         // token group:  tokens  8*ty .. 8*ty+7
    const int tok_base = blockIdx.x * MT;

    // acc[p][j]: packed pair (token 8*ty+2p, 8*ty+2p+1) x expert (4*tx+j)
    unsigned long long acc[4][4];
#pragma unroll
    for (int p = 0; p < 4; ++p)
#pragma unroll
        for (int j = 0; j < 4; ++j) acc[p][j] = 0ULL;

    // ---- global load mapping (per chunk) ----
    // x tile: 128 rows x 16 floats = 512 float4; thread loads rows r and r+64.
    const int xr  = tid >> 2;         // 0..63
    const int xc4 = tid & 3;          // float4 column within chunk (k = 4*xc4+i)
    const float* xg0 = x + (size_t)(tok_base + xr) * HIDDEN + xc4 * 4;
    const float* xg1 = xg0 + (size_t)64 * HIDDEN;
    // w tile: 64 rows x 16 floats = 256 float4; 1 per thread. expert e = tid>>2.
    const int we = tid >> 2;          // 0..63
    const float* wg = w + (size_t)we * HIDDEN + xc4 * 4;

    // ---- swizzled STS offsets (float units) ----
    // x elem (k, t):     off = k*128 + (((t>>2) ^ (k>>2)) << 2) + (t & 3)
    // w elem (k, e) dup: off = k*128 + (((e>>1) ^ (k>>2)) << 2) + ((e & 1) << 1)   [float2 store]
    int xoff0[4], xoff1[4], woff[4];
#pragma unroll
    for (int i = 0; i < 4; ++i) {
        const int k = 4 * xc4 + i;
        const int r2 = xr + 64;
        xoff0[i] = k * 128 + (((xr >> 2) ^ xc4) << 2) + (xr & 3);
        xoff1[i] = k * 128 + (((r2 >> 2) ^ xc4) << 2) + (r2 & 3);
        woff[i]  = k * 128 + (((we >> 1) ^ xc4) << 2) + ((we & 1) << 1);
    }

    // ---- prologue: load + store chunk 0 ----
    float4 rx0 = *(const float4*)xg0;
    float4 rx1 = *(const float4*)xg1;
    float4 rw  = *(const float4*)wg;
    xg0 += KB; xg1 += KB; wg += KB;
    {
        float* xd = xs; float* wd = ws;
        xd[xoff0[0]] = rx0.x; xd[xoff0[1]] = rx0.y; xd[xoff0[2]] = rx0.z; xd[xoff0[3]] = rx0.w;
        xd[xoff1[0]] = rx1.x; xd[xoff1[1]] = rx1.y; xd[xoff1[2]] = rx1.z; xd[xoff1[3]] = rx1.w;
        *(float2*)(wd + woff[0]) = make_float2(rw.x, rw.x);
        *(float2*)(wd + woff[1]) = make_float2(rw.y, rw.y);
        *(float2*)(wd + woff[2]) = make_float2(rw.z, rw.z);
        *(float2*)(wd + woff[3]) = make_float2(rw.w, rw.w);
    }
    __syncthreads();

    // ---- main loop ----
    for (int c = 0; c < NCH; ++c) {
        const bool more = (c + 1 < NCH);
        if (more) {
            rx0 = *(const float4*)xg0;
            rx1 = *(const float4*)xg1;
            rw  = *(const float4*)wg;
            xg0 += KB; xg1 += KB; wg += KB;
        }

        const float* xb_ = xs + (c & 1) * BUFSZ;
        const float* wb_ = ws + (c & 1) * BUFSZ;
#pragma unroll
        for (int k = 0; k < KB; ++k) {
            const int s = k >> 2;
            ulonglong2 xa  = *(const ulonglong2*)(xb_ + k * 128 + (((2 * ty    ) ^ s) << 2));
            ulonglong2 xbv = *(const ulonglong2*)(xb_ + k * 128 + (((2 * ty + 1) ^ s) << 2));
            ulonglong2 wa  = *(const ulonglong2*)(wb_ + k * 128 + (((2 * tx    ) ^ s) << 2));
            ulonglong2 wbv = *(const ulonglong2*)(wb_ + k * 128 + (((2 * tx + 1) ^ s) << 2));
            const unsigned long long xp0 = xa.x,  xp1 = xa.y,  xp2 = xbv.x, xp3 = xbv.y;
            const unsigned long long w0  = wa.x,  w1  = wa.y,  w2  = wbv.x, w3  = wbv.y;
            FMA2(acc[0][0], xp0, w0, acc[0][0]);
            FMA2(acc[0][1], xp0, w1, acc[0][1]);
            FMA2(acc[0][2], xp0, w2, acc[0][2]);
            FMA2(acc[0][3], xp0, w3, acc[0][3]);
            FMA2(acc[1][0], xp1, w0, acc[1][0]);
            FMA2(acc[1][1], xp1, w1, acc[1][1]);
            FMA2(acc[1][2], xp1, w2, acc[1][2]);
            FMA2(acc[1][3], xp1, w3, acc[1][3]);
            FMA2(acc[2][0], xp2, w0, acc[2][0]);
            FMA2(acc[2][1], xp2, w1, acc[2][1]);
            FMA2(acc[2][2], xp2, w2, acc[2][2]);
            FMA2(acc[2][3], xp2, w3, acc[2][3]);
            FMA2(acc[3][0], xp3, w0, acc[3][0]);
            FMA2(acc[3][1], xp3, w1, acc[3][1]);
            FMA2(acc[3][2], xp3, w2, acc[3][2]);
            FMA2(acc[3][3], xp3, w3, acc[3][3]);
        }

        if (more) {
            float* xd = xs + ((c + 1) & 1) * BUFSZ;
            float* wd = ws + ((c + 1) & 1) * BUFSZ;
            xd[xoff0[0]] = rx0.x; xd[xoff0[1]] = rx0.y; xd[xoff0[2]] = rx0.z; xd[xoff0[3]] = rx0.w;
            xd[xoff1[0]] = rx1.x; xd[xoff1[1]] = rx1.y; xd[xoff1[2]] = rx1.z; xd[xoff1[3]] = rx1.w;
            *(float2*)(wd + woff[0]) = make_float2(rw.x, rw.x);
            *(float2*)(wd + woff[1]) = make_float2(rw.y, rw.y);
            *(float2*)(wd + woff[2]) = make_float2(rw.z, rw.z);
            *(float2*)(wd + woff[3]) = make_float2(rw.w, rw.w);
        }
        __syncthreads();
    }

    // ---- epilogue: logits -> smem, per-token top-2 + softmax ----
    float* L = smem;   // [128][65]
    const int t0 = ty * 8;
    const int e0 = tx * 4;
#pragma unroll
    for (int p = 0; p < 4; ++p) {
#pragma unroll
        for (int j = 0; j < 4; ++j) {
            const unsigned long long a = acc[p][j];
            const float lo = __uint_as_float((unsigned int)(a & 0xFFFFFFFFu));
            const float hi = __uint_as_float((unsigned int)(a >> 32));
            L[(t0 + 2 * p    ) * LROW + e0 + j] = lo;
            L[(t0 + 2 * p + 1) * LROW + e0 + j] = hi;
        }
    }
    __syncthreads();

    if (tid < MT) {
        const float* row = L + tid * LROW;
        float m1 = -3.402823466e+38f, m2 = -3.402823466e+38f;
        int i1 = 0, i2 = 0;
#pragma unroll 8
        for (int e = 0; e < NEXPERTS; ++e) {
            const float v = row[e];
            if (v > m1) { m2 = m1; i2 = i1; m1 = v; i1 = e; }
            else if (v > m2) { m2 = v; i2 = e; }
        }
        const float e2 = expf(m2 - m1);
        const float inv = 1.0f / (1.0f + e2);
        const int gt = tok_base + tid;
        out[gt * 2 + 0] = inv;
        out[gt * 2 + 1] = e2 * inv;
        if (out_size >= 4 * TOKENS) {
            out[2 * TOKENS + gt * 2 + 0] = (float)i1;
            out[2 * TOKENS + gt * 2 + 1] = (float)i2;
        }
    }
}

extern "C" void kernel_launch(void* const* d_in, const int* in_sizes, int n_in,
                              void* d_out, int out_size)
{
    (void)in_sizes; (void)n_in;
    const float* x = (const float*)d_in[0];
    const float* w = (const float*)d_in[1];
    Router_4964982194280_kernel<<<TOKENS / MT, NTHREADS>>>(x, w, (float*)d_out, out_size);
}

// round 17
// speedup vs baseline: 1.0061x; 1.0061x over previous
#include <cuda_runtime.h>
#include <math.h>

#define TOKENS   16384
#define HIDDEN   4096
#define NEXPERTS 64
#define MT       128                 // tokens per CTA
#define KB       16                  // k-chunk
#define NCH      (HIDDEN / KB)       // 256 chunks
#define NTHREADS 256
#define LROW     65                  // logits smem row stride (conflict-free scan)
#define BUFSZ    (KB * 128)          // floats per buffer (x: 16k x 128 tok; w: 16k x 128 dup)

#define FMA2(d, a, b, c) \
    asm("fma.rn.f32x2 %0, %1, %2, %3;" : "=l"(d) : "l"(a), "l"(b), "l"(c))

__global__ __launch_bounds__(NTHREADS, 1)
void Router_4964982194280_kernel(const float* __restrict__ x,
                                 const float* __restrict__ w,
                                 float* __restrict__ out, int out_size)
{
    // smem: two double-buffered tiles (x: 2*BUFSZ, w-dup: 2*BUFSZ) = 8192 floats,
    // later overlaid by logits tile 128 x 65 = 8320 floats. 33.3 KB static.
    __shared__ __align__(16) float smem[MT * LROW];
    float* xs = smem;                 // [2][KB][128]  x transposed, swizzled
    float* ws = smem + 2 * BUFSZ;     // [2][KB][128]  w duplicated pairs, swizzled

    const int tid = threadIdx.x;
    const int tx  = tid & 15;         // expert group: experts 4*tx .. 4*tx+3
    const int ty  = tid >> 4;         // token group:  tokens  8*ty .. 8*ty+7
    const int tok_base = blockIdx.x * MT;

    // acc[p][j]: packed pair (token 8*ty+2p, 8*ty+2p+1) x expert (4*tx+j)
    unsigned long long acc[4][4];
#pragma unroll
    for (int p = 0; p < 4; ++p)
#pragma unroll
        for (int j = 0; j < 4; ++j) acc[p][j] = 0ULL;

    // ---- global load mapping (per chunk) ----
    // x tile: 128 rows x 16 floats = 512 float4; thread loads rows r and r+64.
    const int xr  = tid >> 2;         // 0..63
    const int xc4 = tid & 3;          // float4 column within chunk (k = 4*xc4+i)
    const float* xg0 = x + (size_t)(tok_base + xr) * HIDDEN + xc4 * 4;
    const float* xg1 = xg0 + (size_t)64 * HIDDEN;
    // w tile: 64 rows x 16 floats = 256 float4; 1 per thread. expert e = tid>>2.
    const int we = tid >> 2;          // 0..63
    const float* wg = w + (size_t)we * HIDDEN + xc4 * 4;

    // ---- swizzled STS offsets (float units) ----
    // x elem (k, t):     off = k*128 + (((t>>2) ^ (k>>2)) << 2) + (t & 3)
    // w elem (k, e) dup: off = k*128 + (((e>>1) ^ (k>>2)) << 2) + ((e & 1) << 1)   [float2 store]
    int xoff0[4], xoff1[4], woff[4];
#pragma unroll
    for (int i = 0; i < 4; ++i) {
        const int k = 4 * xc4 + i;
        const int r2 = xr + 64;
        xoff0[i] = k * 128 + (((xr >> 2) ^ xc4) << 2) + (xr & 3);
        xoff1[i] = k * 128 + (((r2 >> 2) ^ xc4) << 2) + (r2 & 3);
        woff[i]  = k * 128 + (((we >> 1) ^ xc4) << 2) + ((we & 1) << 1);
    }

    // ---- prologue: load + store chunk 0 ----
    float4 rx0 = *(const float4*)xg0;
    float4 rx1 = *(const float4*)xg1;
    float4 rw  = *(const float4*)wg;
    xg0 += KB; xg1 += KB; wg += KB;
    {
        float* xd = xs; float* wd = ws;
        xd[xoff0[0]] = rx0.x; xd[xoff0[1]] = rx0.y; xd[xoff0[2]] = rx0.z; xd[xoff0[3]] = rx0.w;
        xd[xoff1[0]] = rx1.x; xd[xoff1[1]] = rx1.y; xd[xoff1[2]] = rx1.z; xd[xoff1[3]] = rx1.w;
        *(float2*)(wd + woff[0]) = make_float2(rw.x, rw.x);
        *(float2*)(wd + woff[1]) = make_float2(rw.y, rw.y);
        *(float2*)(wd + woff[2]) = make_float2(rw.z, rw.z);
        *(float2*)(wd + woff[3]) = make_float2(rw.w, rw.w);
    }
    __syncthreads();

    // ---- main loop ----
    for (int c = 0; c < NCH; ++c) {
        const bool more = (c + 1 < NCH);
        if (more) {
            rx0 = *(const float4*)xg0;
            rx1 = *(const float4*)xg1;
            rw  = *(const float4*)wg;
            xg0 += KB; xg1 += KB; wg += KB;
        }

        const float* xb_ = xs + (c & 1) * BUFSZ;
        const float* wb_ = ws + (c & 1) * BUFSZ;
#pragma unroll
        for (int k = 0; k < KB; ++k) {
            const int s = k >> 2;
            ulonglong2 xa  = *(const ulonglong2*)(xb_ + k * 128 + (((2 * ty    ) ^ s) << 2));
            ulonglong2 xbv = *(const ulonglong2*)(xb_ + k * 128 + (((2 * ty + 1) ^ s) << 2));
            ulonglong2 wa  = *(const ulonglong2*)(wb_ + k * 128 + (((2 * tx    ) ^ s) << 2));
            ulonglong2 wbv = *(const ulonglong2*)(wb_ + k * 128 + (((2 * tx + 1) ^ s) << 2));
            const unsigned long long xp0 = xa.x,  xp1 = xa.y,  xp2 = xbv.x, xp3 = xbv.y;
            const unsigned long long w0  = wa.x,  w1  = wa.y,  w2  = wbv.x, w3  = wbv.y;
            FMA2(acc[0][0], xp0, w0, acc[0][0]);
            FMA2(acc[0][1], xp0, w1, acc[0][1]);
            FMA2(acc[0][2], xp0, w2, acc[0][2]);
            FMA2(acc[0][3], xp0, w3, acc[0][3]);
            FMA2(acc[1][0], xp1, w0, acc[1][0]);
            FMA2(acc[1][1], xp1, w1, acc[1][1]);
            FMA2(acc[1][2], xp1, w2, acc[1][2]);
            FMA2(acc[1][3], xp1, w3, acc[1][3]);
            FMA2(acc[2][0], xp2, w0, acc[2][0]);
            FMA2(acc[2][1], xp2, w1, acc[2][1]);
            FMA2(acc[2][2], xp2, w2, acc[2][2]);
            FMA2(acc[2][3], xp2, w3, acc[2][3]);
            FMA2(acc[3][0], xp3, w0, acc[3][0]);
            FMA2(acc[3][1], xp3, w1, acc[3][1]);
            FMA2(acc[3][2], xp3, w2, acc[3][2]);
            FMA2(acc[3][3], xp3, w3, acc[3][3]);
        }

        if (more) {
            float* xd = xs + ((c + 1) & 1) * BUFSZ;
            float* wd = ws + ((c + 1) & 1) * BUFSZ;
            xd[xoff0[0]] = rx0.x; xd[xoff0[1]] = rx0.y; xd[xoff0[2]] = rx0.z; xd[xoff0[3]] = rx0.w;
            xd[xoff1[0]] = rx1.x; xd[xoff1[1]] = rx1.y; xd[xoff1[2]] = rx1.z; xd[xoff1[3]] = rx1.w;
            *(float2*)(wd + woff[0]) = make_float2(rw.x, rw.x);
            *(float2*)(wd + woff[1]) = make_float2(rw.y, rw.y);
            *(float2*)(wd + woff[2]) = make_float2(rw.z, rw.z);
            *(float2*)(wd + woff[3]) = make_float2(rw.w, rw.w);
        }
        __syncthreads();
    }

    // ---- epilogue: logits -> smem, per-token top-2 + softmax ----
    float* L = smem;   // [128][65]
    const int t0 = ty * 8;
    const int e0 = tx * 4;
#pragma unroll
    for (int p = 0; p < 4; ++p) {
#pragma unroll
        for (int j = 0; j < 4; ++j) {
            const unsigned long long a = acc[p][j];
            const float lo = __uint_as_float((unsigned int)(a & 0xFFFFFFFFu));
            const float hi = __uint_as_float((unsigned int)(a >> 32));
            L[(t0 + 2 * p    ) * LROW + e0 + j] = lo;
            L[(t0 + 2 * p + 1) * LROW + e0 + j] = hi;
        }
    }
    __syncthreads();

    if (tid < MT) {
        const float* row = L + tid * LROW;
        float m1 = -3.402823466e+38f, m2 = -3.402823466e+38f;
        int i1 = 0, i2 = 0;
#pragma unroll 8
        for (int e = 0; e < NEXPERTS; ++e) {
            const float v = row[e];
            if (v > m1) { m2 = m1; i2 = i1; m1 = v; i1 = e; }
            else if (v > m2) { m2 = v; i2 = e; }
        }
        const float e2 = expf(m2 - m1);
        const float inv = 1.0f / (1.0f + e2);
        const int gt = tok_base + tid;
        out[gt * 2 + 0] = inv;
        out[gt * 2 + 1] = e2 * inv;
        if (out_size >= 4 * TOKENS) {
            out[2 * TOKENS + gt * 2 + 0] = (float)i1;
            out[2 * TOKENS + gt * 2 + 1] = (float)i2;
        }
    }
}

extern "C" void kernel_launch(void* const* d_in, const int* in_sizes, int n_in,
                              void* d_out, int out_size)
{
    (void)in_sizes; (void)n_in;
    const float* x = (const float*)d_in[0];
    const float* w = (const float*)d_in[1];
    Router_4964982194280_kernel<<<TOKENS / MT, NTHREADS>>>(x, w, (float*)d_out, out_size);
}